// round 1
// baseline (speedup 1.0000x reference)
#include <cuda_runtime.h>

#define BB 8
#define NN 256
#define FF 64
#define ROWS (BB * NN)          // 2048
#define W_ELEMS ((size_t)BB * NN * NN * FF)  // 33,554,432

// Scratch (allocation-free rule: __device__ globals), 16B aligned for float4.
__device__ __align__(16) float g_x1[ROWS * FF];  // relu MLP(n) of x
__device__ __align__(16) float g_s[ROWS * FF];   // relu MLP(s) of x

// ---------------------------------------------------------------------------
// Kernel 1: both MLPs. 64 blocks x 256 threads; each block handles 32 rows.
// All 4 weight matrices (64x64 f32 = 16KB each) staged in SMEM once per block.
// ---------------------------------------------------------------------------
__global__ __launch_bounds__(256) void mlp_kernel(
    const float* __restrict__ x,
    const float* __restrict__ nw1, const float* __restrict__ nb1,
    const float* __restrict__ nw2, const float* __restrict__ nb2,
    const float* __restrict__ sw1, const float* __restrict__ sb1,
    const float* __restrict__ sw2, const float* __restrict__ sb2)
{
    __shared__ float s_nw1[FF * FF];
    __shared__ float s_nw2[FF * FF];
    __shared__ float s_sw1[FF * FF];
    __shared__ float s_sw2[FF * FF];
    __shared__ float s_nb1[FF], s_nb2[FF], s_sb1[FF], s_sb2[FF];
    __shared__ float sx[4][FF];
    __shared__ float sh[4][FF];

    int tid = threadIdx.x;

    // Stage weights via float4 (1024 float4 per matrix, 4 per thread).
    for (int i = tid; i < FF * FF / 4; i += 256) {
        ((float4*)s_nw1)[i] = ((const float4*)nw1)[i];
        ((float4*)s_nw2)[i] = ((const float4*)nw2)[i];
        ((float4*)s_sw1)[i] = ((const float4*)sw1)[i];
        ((float4*)s_sw2)[i] = ((const float4*)sw2)[i];
    }
    if (tid < FF) {
        s_nb1[tid] = nb1[tid];
        s_nb2[tid] = nb2[tid];
        s_sb1[tid] = sb1[tid];
        s_sb2[tid] = sb2[tid];
    }
    __syncthreads();

    int rl = tid >> 6;    // local row 0..3
    int e  = tid & 63;    // feature index
    int base = blockIdx.x * 32;

    for (int c = 0; c < 8; c++) {
        int row = base + c * 4 + rl;
        sx[rl][e] = x[row * FF + e];
        __syncthreads();

        // --- n MLP ---
        float acc = s_nb1[e];
        #pragma unroll
        for (int k = 0; k < FF; k++) acc = fmaf(sx[rl][k], s_nw1[k * FF + e], acc);
        sh[rl][e] = fmaxf(acc, 0.f);
        __syncthreads();

        float acc2 = s_nb2[e];
        #pragma unroll
        for (int k = 0; k < FF; k++) acc2 = fmaf(sh[rl][k], s_nw2[k * FF + e], acc2);
        g_x1[row * FF + e] = fmaxf(acc2, 0.f);
        __syncthreads();   // protect sh before reuse

        // --- s MLP ---
        float accs = s_sb1[e];
        #pragma unroll
        for (int k = 0; k < FF; k++) accs = fmaf(sx[rl][k], s_sw1[k * FF + e], accs);
        sh[rl][e] = fmaxf(accs, 0.f);
        __syncthreads();

        float accs2 = s_sb2[e];
        #pragma unroll
        for (int k = 0; k < FF; k++) accs2 = fmaf(sh[rl][k], s_sw2[k * FF + e], accs2);
        g_s[row * FF + e] = fmaxf(accs2, 0.f);
        __syncthreads();   // protect sx/sh before next chunk
    }
}

// ---------------------------------------------------------------------------
// Kernel 2: fused L1-normalize + einsum + W copy + add s-MLP.
// One block per (b,i). 256 threads = 16 j-groups x 16 float4-lanes (64 feats).
// W is streamed (__ldcs / __stcs) so x1[b] (64KB, reused by 256 blocks) stays
// resident in L2.
// ---------------------------------------------------------------------------
__global__ __launch_bounds__(256) void agg_kernel(
    const float* __restrict__ A,
    const float4* __restrict__ W,
    float4* __restrict__ outW,
    float* __restrict__ outX2)
{
    int bi = blockIdx.x;          // b*256 + i
    int b  = bi >> 8;
    int tid = threadIdx.x;

    __shared__ float sAn[NN];
    __shared__ float4 red[256];
    __shared__ float warp_s[8];
    __shared__ float sden;

    // L1 denom over the A row (each thread owns one j).
    float a = A[bi * NN + tid];
    float v = fabsf(a);
    #pragma unroll
    for (int off = 16; off; off >>= 1) v += __shfl_xor_sync(0xffffffffu, v, off);
    if ((tid & 31) == 0) warp_s[tid >> 5] = v;
    __syncthreads();
    if (tid == 0) {
        float t = 0.f;
        #pragma unroll
        for (int w = 0; w < 8; w++) t += warp_s[w];
        sden = fmaxf(t, 1e-12f);
    }
    __syncthreads();
    sAn[tid] = a / sden;
    __syncthreads();

    const float4* Wr  = W    + (size_t)bi * (NN * 16);
    float4*       Or  = outW + (size_t)bi * (NN * 16);
    const float4* x1b = ((const float4*)g_x1) + (size_t)b * (NN * 16);

    int e4 = tid & 15;    // float4 lane (covers features e4*4 .. e4*4+3)
    int jg = tid >> 4;    // j group 0..15

    float4 acc = make_float4(0.f, 0.f, 0.f, 0.f);
    #pragma unroll 4
    for (int jj = 0; jj < 16; jj++) {
        int j = jg + jj * 16;
        float4 w   = __ldcs(&Wr[j * 16 + e4]);
        __stcs(&Or[j * 16 + e4], w);
        float4 x1v = x1b[j * 16 + e4];
        float  t   = sAn[j];
        acc.x = fmaf(t * w.x, x1v.x, acc.x);
        acc.y = fmaf(t * w.y, x1v.y, acc.y);
        acc.z = fmaf(t * w.z, x1v.z, acc.z);
        acc.w = fmaf(t * w.w, x1v.w, acc.w);
    }

    red[tid] = acc;
    __syncthreads();

    if (tid < 16) {
        float4 r = red[tid];
        #pragma unroll
        for (int k = 1; k < 16; k++) {
            float4 t = red[k * 16 + tid];
            r.x += t.x; r.y += t.y; r.z += t.z; r.w += t.w;
        }
        float4 sv = ((const float4*)g_s)[bi * 16 + tid];
        r.x += sv.x; r.y += sv.y; r.z += sv.z; r.w += sv.w;
        ((float4*)outX2)[bi * 16 + tid] = r;
    }
}

// ---------------------------------------------------------------------------
extern "C" void kernel_launch(void* const* d_in, const int* in_sizes, int n_in,
                              void* d_out, int out_size)
{
    const float* A   = (const float*)d_in[0];
    const float* W   = (const float*)d_in[1];
    const float* x   = (const float*)d_in[2];
    const float* nw1 = (const float*)d_in[3];
    const float* nb1 = (const float*)d_in[4];
    const float* nw2 = (const float*)d_in[5];
    const float* nb2 = (const float*)d_in[6];
    const float* sw1 = (const float*)d_in[7];
    const float* sb1 = (const float*)d_in[8];
    const float* sw2 = (const float*)d_in[9];
    const float* sb2 = (const float*)d_in[10];

    float* outW  = (float*)d_out;            // W passthrough, 33,554,432 floats
    float* outX2 = (float*)d_out + W_ELEMS;  // x2, 131,072 floats

    mlp_kernel<<<64, 256>>>(x, nw1, nb1, nw2, nb2, sw1, sb1, sw2, sb2);
    agg_kernel<<<ROWS, 256>>>(A, (const float4*)W, (float4*)outW, outX2);
}

// round 2
// speedup vs baseline: 1.2320x; 1.2320x over previous
#include <cuda_runtime.h>

#define BB 8
#define NN 256
#define FF 64
#define ROWS (BB * NN)          // 2048
#define W_ELEMS ((size_t)BB * NN * NN * FF)  // 33,554,432

// Scratch (allocation-free rule: __device__ globals), 16B aligned for float4.
__device__ __align__(16) float g_x1[ROWS * FF];  // relu MLP(n) of x
__device__ __align__(16) float g_s[ROWS * FF];   // relu MLP(s) of x

// ---------------------------------------------------------------------------
// Kernel 1: both MLPs. 256 blocks x 256 threads; each block handles 8 rows
// (4 rows per pass, 2 passes). All 4 weight matrices (16KB each) staged in
// SMEM once per block; weights live in L2 so restaging is cheap.
// ---------------------------------------------------------------------------
__global__ __launch_bounds__(256) void mlp_kernel(
    const float* __restrict__ x,
    const float* __restrict__ nw1, const float* __restrict__ nb1,
    const float* __restrict__ nw2, const float* __restrict__ nb2,
    const float* __restrict__ sw1, const float* __restrict__ sb1,
    const float* __restrict__ sw2, const float* __restrict__ sb2)
{
    __shared__ float s_nw1[FF * FF];
    __shared__ float s_nw2[FF * FF];
    __shared__ float s_sw1[FF * FF];
    __shared__ float s_sw2[FF * FF];
    __shared__ float s_nb1[FF], s_nb2[FF], s_sb1[FF], s_sb2[FF];
    __shared__ float sx[4][FF];
    __shared__ float sh[4][FF];

    int tid = threadIdx.x;

    // Stage weights via float4 (1024 float4 per matrix, 4 per thread).
    for (int i = tid; i < FF * FF / 4; i += 256) {
        ((float4*)s_nw1)[i] = ((const float4*)nw1)[i];
        ((float4*)s_nw2)[i] = ((const float4*)nw2)[i];
        ((float4*)s_sw1)[i] = ((const float4*)sw1)[i];
        ((float4*)s_sw2)[i] = ((const float4*)sw2)[i];
    }
    if (tid < FF) {
        s_nb1[tid] = nb1[tid];
        s_nb2[tid] = nb2[tid];
        s_sb1[tid] = sb1[tid];
        s_sb2[tid] = sb2[tid];
    }
    __syncthreads();

    int rl = tid >> 6;    // local row 0..3
    int e  = tid & 63;    // feature index
    int base = blockIdx.x * 8;   // 8 rows per block

    for (int c = 0; c < 2; c++) {
        int row = base + c * 4 + rl;
        sx[rl][e] = x[row * FF + e];
        __syncthreads();

        // --- n MLP ---
        float acc = s_nb1[e];
        #pragma unroll
        for (int k = 0; k < FF; k++) acc = fmaf(sx[rl][k], s_nw1[k * FF + e], acc);
        sh[rl][e] = fmaxf(acc, 0.f);
        __syncthreads();

        float acc2 = s_nb2[e];
        #pragma unroll
        for (int k = 0; k < FF; k++) acc2 = fmaf(sh[rl][k], s_nw2[k * FF + e], acc2);
        g_x1[row * FF + e] = fmaxf(acc2, 0.f);
        __syncthreads();   // protect sh before reuse

        // --- s MLP ---
        float accs = s_sb1[e];
        #pragma unroll
        for (int k = 0; k < FF; k++) accs = fmaf(sx[rl][k], s_sw1[k * FF + e], accs);
        sh[rl][e] = fmaxf(accs, 0.f);
        __syncthreads();

        float accs2 = s_sb2[e];
        #pragma unroll
        for (int k = 0; k < FF; k++) accs2 = fmaf(sh[rl][k], s_sw2[k * FF + e], accs2);
        g_s[row * FF + e] = fmaxf(accs2, 0.f);
        __syncthreads();   // protect sx/sh before next chunk
    }
}

// ---------------------------------------------------------------------------
// Kernel 2: fused L1-normalize + einsum + W copy + add s-MLP.
// One block per (b,i). 256 threads = 16 j-groups x 16 float4-lanes (64 feats).
// __launch_bounds__(256, 8) caps registers at 32 -> 8 blocks/SM (full
// occupancy) so enough loads are in flight to saturate HBM.
// W is streamed (__ldcs / __stcs) so x1[b] (64KB, reused by 256 blocks) stays
// resident in L2.
// ---------------------------------------------------------------------------
__global__ __launch_bounds__(256, 8) void agg_kernel(
    const float* __restrict__ A,
    const float4* __restrict__ W,
    float4* __restrict__ outW,
    float* __restrict__ outX2)
{
    int bi = blockIdx.x;          // b*256 + i
    int b  = bi >> 8;
    int tid = threadIdx.x;

    __shared__ float sAn[NN];
    __shared__ float4 red[256];
    __shared__ float warp_s[8];
    __shared__ float sden;

    // L1 denom over the A row (each thread owns one j).
    float a = A[bi * NN + tid];
    float v = fabsf(a);
    #pragma unroll
    for (int off = 16; off; off >>= 1) v += __shfl_xor_sync(0xffffffffu, v, off);
    if ((tid & 31) == 0) warp_s[tid >> 5] = v;
    __syncthreads();
    if (tid == 0) {
        float t = 0.f;
        #pragma unroll
        for (int w = 0; w < 8; w++) t += warp_s[w];
        sden = fmaxf(t, 1e-12f);
    }
    __syncthreads();
    sAn[tid] = a / sden;
    __syncthreads();

    const float4* Wr  = W    + (size_t)bi * (NN * 16);
    float4*       Or  = outW + (size_t)bi * (NN * 16);
    const float4* x1b = ((const float4*)g_x1) + (size_t)b * (NN * 16);

    int e4 = tid & 15;    // float4 lane (covers features e4*4 .. e4*4+3)
    int jg = tid >> 4;    // j group 0..15

    float4 acc = make_float4(0.f, 0.f, 0.f, 0.f);
    #pragma unroll 4
    for (int jj = 0; jj < 16; jj++) {
        int j = jg + jj * 16;
        float4 w   = __ldcs(&Wr[j * 16 + e4]);
        __stcs(&Or[j * 16 + e4], w);
        float4 x1v = x1b[j * 16 + e4];
        float  t   = sAn[j];
        acc.x = fmaf(t * w.x, x1v.x, acc.x);
        acc.y = fmaf(t * w.y, x1v.y, acc.y);
        acc.z = fmaf(t * w.z, x1v.z, acc.z);
        acc.w = fmaf(t * w.w, x1v.w, acc.w);
    }

    red[tid] = acc;
    __syncthreads();

    if (tid < 16) {
        float4 r = red[tid];
        #pragma unroll
        for (int k = 1; k < 16; k++) {
            float4 t = red[k * 16 + tid];
            r.x += t.x; r.y += t.y; r.z += t.z; r.w += t.w;
        }
        float4 sv = ((const float4*)g_s)[bi * 16 + tid];
        r.x += sv.x; r.y += sv.y; r.z += sv.z; r.w += sv.w;
        ((float4*)outX2)[bi * 16 + tid] = r;
    }
}

// ---------------------------------------------------------------------------
extern "C" void kernel_launch(void* const* d_in, const int* in_sizes, int n_in,
                              void* d_out, int out_size)
{
    const float* A   = (const float*)d_in[0];
    const float* W   = (const float*)d_in[1];
    const float* x   = (const float*)d_in[2];
    const float* nw1 = (const float*)d_in[3];
    const float* nb1 = (const float*)d_in[4];
    const float* nw2 = (const float*)d_in[5];
    const float* nb2 = (const float*)d_in[6];
    const float* sw1 = (const float*)d_in[7];
    const float* sb1 = (const float*)d_in[8];
    const float* sw2 = (const float*)d_in[9];
    const float* sb2 = (const float*)d_in[10];

    float* outW  = (float*)d_out;            // W passthrough, 33,554,432 floats
    float* outX2 = (float*)d_out + W_ELEMS;  // x2, 131,072 floats

    mlp_kernel<<<256, 256>>>(x, nw1, nb1, nw2, nb2, sw1, sb1, sw2, sb2);
    agg_kernel<<<ROWS, 256>>>(A, (const float4*)W, (float4*)outW, outX2);
}

// round 3
// speedup vs baseline: 1.4233x; 1.1552x over previous
#include <cuda_runtime.h>
#include <cstdint>

#define BB 8
#define NN 256
#define FF 64
#define ROWS (BB * NN)          // 2048
#define W_ELEMS ((size_t)BB * NN * NN * FF)  // 33,554,432

// Scratch (allocation-free rule: __device__ globals), 16B aligned for float4.
__device__ __align__(16) float g_x1[ROWS * FF];  // relu MLP(n) of x
__device__ __align__(16) float g_s[ROWS * FF];   // relu MLP(s) of x

// ---------------------------------------------------------------------------
// PTX helpers
// ---------------------------------------------------------------------------
__device__ __forceinline__ uint32_t s2u(const void* p) {
    return (uint32_t)__cvta_generic_to_shared(p);
}
__device__ __forceinline__ void mbar_init(uint32_t mbar, uint32_t count) {
    asm volatile("mbarrier.init.shared.b64 [%0], %1;" :: "r"(mbar), "r"(count) : "memory");
}
__device__ __forceinline__ void mbar_expect_tx(uint32_t mbar, uint32_t bytes) {
    asm volatile("mbarrier.arrive.expect_tx.shared.b64 _, [%0], %1;"
                 :: "r"(mbar), "r"(bytes) : "memory");
}
__device__ __forceinline__ void mbar_wait(uint32_t mbar, uint32_t parity) {
    uint32_t done;
    asm volatile(
        "{\n\t.reg .pred p;\n\t"
        "mbarrier.try_wait.parity.acquire.cta.shared::cta.b64 p, [%1], %2;\n\t"
        "selp.b32 %0, 1, 0, p;\n\t}"
        : "=r"(done) : "r"(mbar), "r"(parity) : "memory");
    while (!done) {
        asm volatile(
            "{\n\t.reg .pred p;\n\t"
            "mbarrier.try_wait.parity.acquire.cta.shared::cta.b64 p, [%1], %2, 0x989680;\n\t"
            "selp.b32 %0, 1, 0, p;\n\t}"
            : "=r"(done) : "r"(mbar), "r"(parity) : "memory");
    }
}
__device__ __forceinline__ void bulk_g2s(uint32_t dst_smem, const void* src,
                                         uint32_t bytes, uint32_t mbar) {
    asm volatile(
        "cp.async.bulk.shared::cluster.global.mbarrier::complete_tx::bytes "
        "[%0], [%1], %2, [%3];"
        :: "r"(dst_smem), "l"(src), "r"(bytes), "r"(mbar) : "memory");
}
__device__ __forceinline__ void bulk_s2g(void* dst, uint32_t src_smem, uint32_t bytes) {
    asm volatile("cp.async.bulk.global.shared::cta.bulk_group [%0], [%1], %2;"
                 :: "l"(dst), "r"(src_smem), "r"(bytes) : "memory");
}
__device__ __forceinline__ void bulk_commit() {
    asm volatile("cp.async.bulk.commit_group;" ::: "memory");
}
__device__ __forceinline__ void bulk_wait_all() {
    asm volatile("cp.async.bulk.wait_group 0;" ::: "memory");
}
__device__ __forceinline__ void fence_async() {
    asm volatile("fence.proxy.async.shared::cta;" ::: "memory");
}

// ---------------------------------------------------------------------------
// Kernel 1: both MLPs. 128 blocks x 256 threads; 16 rows per block.
// Threads = (e 0..63) x (g 0..3); thread (g,e) computes output feature e for
// rows 4g..4g+3 -> each weight element is read from SMEM once per 4 rows.
// x and hidden kept TRANSPOSED in SMEM ([k][row], padded to 17) so the 4-row
// inner products use broadcast LDS.
// ---------------------------------------------------------------------------
__global__ __launch_bounds__(256) void mlp_kernel(
    const float* __restrict__ x,
    const float* __restrict__ nw1, const float* __restrict__ nb1,
    const float* __restrict__ nw2, const float* __restrict__ nb2,
    const float* __restrict__ sw1, const float* __restrict__ sb1,
    const float* __restrict__ sw2, const float* __restrict__ sb2)
{
    __shared__ float s_w1[2][FF * FF];
    __shared__ float s_w2[2][FF * FF];
    __shared__ float s_b1[2][FF], s_b2[2][FF];
    __shared__ float sxT[FF][17];   // [k][row], padded
    __shared__ float shT[FF][17];   // hidden transposed

    int tid = threadIdx.x;
    int e = tid & 63;
    int g = tid >> 6;        // row quad 0..3

    for (int i = tid; i < FF * FF / 4; i += 256) {
        ((float4*)s_w1[0])[i] = ((const float4*)nw1)[i];
        ((float4*)s_w2[0])[i] = ((const float4*)nw2)[i];
        ((float4*)s_w1[1])[i] = ((const float4*)sw1)[i];
        ((float4*)s_w2[1])[i] = ((const float4*)sw2)[i];
    }
    if (tid < FF) {
        s_b1[0][tid] = nb1[tid];
        s_b2[0][tid] = nb2[tid];
        s_b1[1][tid] = sb1[tid];
        s_b2[1][tid] = sb2[tid];
    }

    int base = blockIdx.x * 16;     // 16 rows per block
    // Load x[base..base+15][0..63] transposed into sxT.
    {
        float4 v = ((const float4*)(x + (size_t)base * FF))[tid]; // 1024 floats total
        int r  = (tid * 4) / FF;    // row 0..15
        int k0 = (tid * 4) % FF;
        sxT[k0 + 0][r] = v.x;
        sxT[k0 + 1][r] = v.y;
        sxT[k0 + 2][r] = v.z;
        sxT[k0 + 3][r] = v.w;
    }
    __syncthreads();

    for (int p = 0; p < 2; p++) {   // p=0: n-MLP -> g_x1 ; p=1: s-MLP -> g_s
        float a0 = s_b1[p][e], a1 = a0, a2 = a0, a3 = a0;
        #pragma unroll
        for (int k = 0; k < FF; k++) {
            float w = s_w1[p][k * FF + e];
            a0 = fmaf(w, sxT[k][4 * g + 0], a0);
            a1 = fmaf(w, sxT[k][4 * g + 1], a1);
            a2 = fmaf(w, sxT[k][4 * g + 2], a2);
            a3 = fmaf(w, sxT[k][4 * g + 3], a3);
        }
        shT[e][4 * g + 0] = fmaxf(a0, 0.f);
        shT[e][4 * g + 1] = fmaxf(a1, 0.f);
        shT[e][4 * g + 2] = fmaxf(a2, 0.f);
        shT[e][4 * g + 3] = fmaxf(a3, 0.f);
        __syncthreads();

        float c0 = s_b2[p][e], c1 = c0, c2 = c0, c3 = c0;
        #pragma unroll
        for (int k = 0; k < FF; k++) {
            float w = s_w2[p][k * FF + e];
            c0 = fmaf(w, shT[k][4 * g + 0], c0);
            c1 = fmaf(w, shT[k][4 * g + 1], c1);
            c2 = fmaf(w, shT[k][4 * g + 2], c2);
            c3 = fmaf(w, shT[k][4 * g + 3], c3);
        }
        float* out = p ? g_s : g_x1;
        out[(size_t)(base + 4 * g + 0) * FF + e] = fmaxf(c0, 0.f);
        out[(size_t)(base + 4 * g + 1) * FF + e] = fmaxf(c1, 0.f);
        out[(size_t)(base + 4 * g + 2) * FF + e] = fmaxf(c2, 0.f);
        out[(size_t)(base + 4 * g + 3) * FF + e] = fmaxf(c3, 0.f);
        __syncthreads();    // protect shT before p=1
    }
}

// ---------------------------------------------------------------------------
// Kernel 2: fused L1-normalize + einsum + W copy + add s-MLP.
// One block per (b,i). W row (64KB) is streamed through SMEM in four 16KB
// tiles with cp.async.bulk (double buffered): bulk gmem->smem load, compute
// einsum from SMEM, bulk smem->gmem store of the same tile. DRAM sees 16KB
// contiguous bursts instead of interleaved 512B read/write transactions.
// ---------------------------------------------------------------------------
#define TILE_J 64
#define TILE_BYTES (TILE_J * FF * 4)   // 16384
#define NTILES (NN / TILE_J)           // 4

__global__ __launch_bounds__(256) void agg_kernel(
    const float* __restrict__ A,
    const char* __restrict__ W,
    char* __restrict__ outW,
    float* __restrict__ outX2)
{
    __shared__ float sAn[NN];
    __shared__ float4 red[256];
    __shared__ float warp_s[8];
    __shared__ float sden;
    __shared__ __align__(128) char tile[2][TILE_BYTES];
    __shared__ __align__(8) unsigned long long mbar_store[2];

    int bi = blockIdx.x;          // b*256 + i
    int b  = bi >> 8;
    int tid = threadIdx.x;

    uint32_t mb0 = s2u(&mbar_store[0]);
    uint32_t mb1 = s2u(&mbar_store[1]);
    uint32_t tile_u32[2] = { s2u(&tile[0][0]), s2u(&tile[1][0]) };

    if (tid == 0) {
        mbar_init(mb0, 1);
        mbar_init(mb1, 1);
    }

    // L1 denom over the A row (each thread owns one j).
    float a = A[(size_t)bi * NN + tid];
    float v = fabsf(a);
    #pragma unroll
    for (int off = 16; off; off >>= 1) v += __shfl_xor_sync(0xffffffffu, v, off);
    if ((tid & 31) == 0) warp_s[tid >> 5] = v;
    __syncthreads();     // also makes mbarrier init visible before any TMA
    if (tid == 0) {
        float t = 0.f;
        #pragma unroll
        for (int w = 0; w < 8; w++) t += warp_s[w];
        sden = fmaxf(t, 1e-12f);
        // Prologue: kick off tile 0 load.
        mbar_expect_tx(mb0, TILE_BYTES);
        bulk_g2s(tile_u32[0], W + (size_t)bi * (NN * FF * 4), TILE_BYTES, mb0);
    }
    __syncthreads();
    sAn[tid] = a / sden;
    __syncthreads();

    const char* Wrow = W    + (size_t)bi * (NN * FF * 4);
    char*       Orow = outW + (size_t)bi * (NN * FF * 4);
    const float4* x1b = ((const float4*)g_x1) + (size_t)b * (NN * 16);

    int e4 = tid & 15;    // float4 lane (features e4*4 .. e4*4+3)
    int jg = tid >> 4;    // j group 0..15 within tile

    float4 acc = make_float4(0.f, 0.f, 0.f, 0.f);

    uint32_t mb[2] = { mb0, mb1 };

    #pragma unroll
    for (int t = 0; t < NTILES; t++) {
        int s  = t & 1;
        int ph = (t >> 1) & 1;
        mbar_wait(mb[s], ph);   // tile t resident in stage s

        if (tid == 0) {
            if (t + 1 < NTILES) {
                // Stage s^1: previous store (tile t-1) must have drained and
                // consumers finished (end-of-iter syncthreads of t-1).
                bulk_wait_all();
                mbar_expect_tx(mb[s ^ 1], TILE_BYTES);
                bulk_g2s(tile_u32[s ^ 1], Wrow + (size_t)(t + 1) * TILE_BYTES,
                         TILE_BYTES, mb[s ^ 1]);
            }
            fence_async();
            bulk_s2g(Orow + (size_t)t * TILE_BYTES, tile_u32[s], TILE_BYTES);
            bulk_commit();
        }

        const float4* Wt = (const float4*)tile[s];
        #pragma unroll
        for (int k = 0; k < TILE_J / 16; k++) {
            int jl = jg + 16 * k;          // j within tile
            int j  = t * TILE_J + jl;
            float4 w   = Wt[jl * 16 + e4];
            float4 x1v = x1b[j * 16 + e4];
            float  tt  = sAn[j];
            acc.x = fmaf(tt * w.x, x1v.x, acc.x);
            acc.y = fmaf(tt * w.y, x1v.y, acc.y);
            acc.z = fmaf(tt * w.z, x1v.z, acc.z);
            acc.w = fmaf(tt * w.w, x1v.w, acc.w);
        }
        __syncthreads();   // consumers done with stage s before it is reloaded
    }

    red[tid] = acc;
    __syncthreads();

    if (tid < 16) {
        float4 r = red[tid];
        #pragma unroll
        for (int k = 1; k < 16; k++) {
            float4 t = red[k * 16 + tid];
            r.x += t.x; r.y += t.y; r.z += t.z; r.w += t.w;
        }
        float4 sv = ((const float4*)g_s)[bi * 16 + tid];
        r.x += sv.x; r.y += sv.y; r.z += sv.z; r.w += sv.w;
        ((float4*)outX2)[bi * 16 + tid] = r;
    }

    if (tid == 0) bulk_wait_all();   // ensure final W-tile store drained
}

// ---------------------------------------------------------------------------
extern "C" void kernel_launch(void* const* d_in, const int* in_sizes, int n_in,
                              void* d_out, int out_size)
{
    const float* A   = (const float*)d_in[0];
    const float* W   = (const float*)d_in[1];
    const float* x   = (const float*)d_in[2];
    const float* nw1 = (const float*)d_in[3];
    const float* nb1 = (const float*)d_in[4];
    const float* nw2 = (const float*)d_in[5];
    const float* nb2 = (const float*)d_in[6];
    const float* sw1 = (const float*)d_in[7];
    const float* sb1 = (const float*)d_in[8];
    const float* sw2 = (const float*)d_in[9];
    const float* sb2 = (const float*)d_in[10];

    float* outW  = (float*)d_out;            // W passthrough, 33,554,432 floats
    float* outX2 = (float*)d_out + W_ELEMS;  // x2, 131,072 floats

    mlp_kernel<<<128, 256>>>(x, nw1, nb1, nw2, nb2, sw1, sb1, sw2, sb2);
    agg_kernel<<<ROWS, 256>>>(A, (const char*)W, (char*)outW, outX2);
}